// round 3
// baseline (speedup 1.0000x reference)
#include <cuda_runtime.h>
#include <cuda_bf16.h>
#include <mma.h>

using namespace nvcuda;

#define NROWS 4096
#define DIM   1024
#define BM    64
#define KC    64
#define LDA   72   // bf16 elems, padded
#define LDC   68   // float elems, padded
#define TILES 64   // 4096 / 64

// Scratch (static __device__ allowed; no runtime allocation)
__device__ __align__(16) __nv_bfloat16 g_fbf[(size_t)NROWS * DIM];
__device__ float g_rowsum[NROWS];
__device__ float g_possum;

// ---------------- Kernel 1: L2 normalize rows, fp32 -> bf16; zero accumulators
__global__ void normalize_kernel(const float* __restrict__ feat) {
    int row = blockIdx.x;
    int tid = threadIdx.x;
    const float* fr = feat + (size_t)row * DIM;
    float ss = 0.f;
    #pragma unroll
    for (int i = tid; i < DIM; i += 256) { float v = fr[i]; ss += v * v; }
    __shared__ float sh[8];
    #pragma unroll
    for (int o = 16; o > 0; o >>= 1) ss += __shfl_down_sync(0xffffffffu, ss, o);
    if ((tid & 31) == 0) sh[tid >> 5] = ss;
    __syncthreads();
    if (tid < 32) {
        float v = (tid < 8) ? sh[tid] : 0.f;
        #pragma unroll
        for (int o = 4; o > 0; o >>= 1) v += __shfl_down_sync(0xffffffffu, v, o);
        if (tid == 0) sh[0] = v;
    }
    __syncthreads();
    float inv = 1.0f / fmaxf(sqrtf(sh[0]), 1e-12f);
    __nv_bfloat16* out = g_fbf + (size_t)row * DIM;
    #pragma unroll
    for (int i = tid; i < DIM; i += 256) out[i] = __float2bfloat16(fr[i] * inv);
    if (tid == 0) {
        g_rowsum[row] = 0.f;
        if (row == 0) g_possum = 0.f;
    }
}

// ---------------- Kernel 2: tiled f·f^T (upper triangle), fused exp + reductions
__global__ void sim_kernel(const int* __restrict__ targets) {
    int bi = blockIdx.y, bj = blockIdx.x;
    if (bj < bi) return;   // symmetry: only upper-triangular tiles
    int tid = threadIdx.x;

    __shared__ __align__(16) __nv_bfloat16 As[BM * LDA];
    __shared__ __align__(16) __nv_bfloat16 Bs[BM * LDA];
    __shared__ float Cs[BM * LDC];
    __shared__ int Li[BM], Lj[BM];
    __shared__ float pred[8];

    if (tid < BM)            Li[tid]      = targets[bi * BM + tid];
    else if (tid < 2 * BM)   Lj[tid - BM] = targets[bj * BM + (tid - BM)];

    wmma::fragment<wmma::accumulator, 16, 16, 16, float> acc[2];
    wmma::fill_fragment(acc[0], 0.f);
    wmma::fill_fragment(acc[1], 0.f);
    int warp = tid >> 5;
    int tr   = warp >> 1;          // 16-row strip of this warp
    int tc0  = (warp & 1) * 2;     // first of two 16-col strips

    const __nv_bfloat16* FA = g_fbf + (size_t)bi * BM * DIM;
    const __nv_bfloat16* FB = g_fbf + (size_t)bj * BM * DIM;

    for (int k0 = 0; k0 < DIM; k0 += KC) {
        // cooperative load: 64x64 bf16 per operand, vectorized 16B
        #pragma unroll
        for (int v = tid; v < BM * KC / 8; v += 256) {
            int r = v >> 3, c8 = v & 7;
            *(uint4*)&As[r * LDA + c8 * 8] =
                *(const uint4*)&FA[(size_t)r * DIM + k0 + c8 * 8];
            *(uint4*)&Bs[r * LDA + c8 * 8] =
                *(const uint4*)&FB[(size_t)r * DIM + k0 + c8 * 8];
        }
        __syncthreads();
        wmma::fragment<wmma::matrix_a, 16, 16, 16, __nv_bfloat16, wmma::row_major> a;
        wmma::fragment<wmma::matrix_b, 16, 16, 16, __nv_bfloat16, wmma::col_major> b;
        #pragma unroll
        for (int kk = 0; kk < KC / 16; kk++) {
            wmma::load_matrix_sync(a, &As[(tr * 16) * LDA + kk * 16], LDA);
            #pragma unroll
            for (int t = 0; t < 2; t++) {
                wmma::load_matrix_sync(b, &Bs[((tc0 + t) * 16) * LDA + kk * 16], LDA);
                wmma::mma_sync(acc[t], a, b, acc[t]);
            }
        }
        __syncthreads();
    }
    wmma::store_matrix_sync(&Cs[(tr * 16) * LDC + tc0 * 16], acc[0], LDC, wmma::mem_row_major);
    wmma::store_matrix_sync(&Cs[(tr * 16) * LDC + (tc0 + 1) * 16], acc[1], LDC, wmma::mem_row_major);
    __syncthreads();

    // Row pass: exp, row sums for global rows of bi, positive-pair sum.
    // Also overwrite Cs with exp values for reuse in the column pass.
    int r = tid >> 2, q = tid & 3;
    float rsum = 0.f, psum = 0.f;
    int li = Li[r];
    int gi = bi * BM + r;
    #pragma unroll
    for (int cc = 0; cc < 16; cc++) {
        int c = q * 16 + cc;
        float e;
        if (bi == bj && r == c) {
            e = 0.f;                      // exact diagonal exclusion
        } else {
            e = __expf(Cs[r * LDC + c] * 10.f);   // /temperature
            if (li == Lj[c]) psum += e;
        }
        rsum += e;
        Cs[r * LDC + c] = e;
    }
    rsum += __shfl_xor_sync(0xffffffffu, rsum, 1);
    rsum += __shfl_xor_sync(0xffffffffu, rsum, 2);
    if (q == 0) atomicAdd(&g_rowsum[gi], rsum);

    // Column pass (symmetric contribution) for off-diagonal tiles
    if (bi != bj) {
        __syncthreads();
        int c = tid >> 2;
        float csum = 0.f;
        #pragma unroll
        for (int rr = 0; rr < 16; rr++)
            csum += Cs[(q * 16 + rr) * LDC + c];
        csum += __shfl_xor_sync(0xffffffffu, csum, 1);
        csum += __shfl_xor_sync(0xffffffffu, csum, 2);
        if (q == 0) atomicAdd(&g_rowsum[bj * BM + c], csum);
        psum *= 2.f;   // (i,j) and (j,i) both contribute
    }

    // Block-reduce positive-pair sum -> one atomic per block
    #pragma unroll
    for (int o = 16; o > 0; o >>= 1) psum += __shfl_down_sync(0xffffffffu, psum, o);
    if ((tid & 31) == 0) pred[warp] = psum;
    __syncthreads();
    if (tid < 32) {
        float v = (tid < 8) ? pred[tid] : 0.f;
        #pragma unroll
        for (int o = 4; o > 0; o >>= 1) v += __shfl_down_sync(0xffffffffu, v, o);
        if (tid == 0) atomicAdd(&g_possum, v);
    }
}

// ---------------- Kernel 3: finalize (double-precision logs for the scalar)
__global__ void finalize_kernel(float* __restrict__ out) {
    int tid = threadIdx.x;
    double s = 0.0;
    for (int i = tid; i < NROWS; i += 256) s += log((double)g_rowsum[i]);
    __shared__ double sh[8];
    #pragma unroll
    for (int o = 16; o > 0; o >>= 1) s += __shfl_down_sync(0xffffffffu, s, o);
    if ((tid & 31) == 0) sh[tid >> 5] = s;
    __syncthreads();
    if (tid == 0) {
        double t = 0.0;
        #pragma unroll
        for (int i = 0; i < 8; i++) t += sh[i];
        // total = mean row-logsumexp + ( - log(sum exp over positive pairs) )
        out[0] = (float)(t / (double)NROWS - log((double)g_possum));
    }
}

extern "C" void kernel_launch(void* const* d_in, const int* in_sizes, int n_in,
                              void* d_out, int out_size) {
    const float* feat = (const float*)d_in[0];
    const int* tgt = (const int*)d_in[1];
    normalize_kernel<<<NROWS, 256>>>(feat);
    dim3 grid(TILES, TILES);
    sim_kernel<<<grid, 256>>>(tgt);
    finalize_kernel<<<1, 256>>>((float*)d_out);
}

// round 4
// speedup vs baseline: 1.3670x; 1.3670x over previous
#include <cuda_runtime.h>
#include <cuda_bf16.h>

#define NROWS 4096
#define DIM   1024
#define BT    128          // block tile (M and N)
#define KC    32           // k chunk per pipeline stage
#define NCHUNK (DIM / KC)  // 32
#define LDA   40           // bf16 elems per row in smem (32 + 8 pad, 80B rows)
#define BUFSZ (BT * LDA)   // elems per stage per operand
#define GTILES (NROWS / BT) // 32

__device__ __align__(16) __nv_bfloat16 g_fbf[(size_t)NROWS * DIM];
__device__ float g_rowsum[NROWS];
__device__ float g_possum;

// ---------------- Kernel 1: L2 normalize rows fp32 -> bf16 (1 float4/thread)
__global__ __launch_bounds__(256) void normalize_kernel(const float* __restrict__ feat) {
    int row = blockIdx.x;
    int tid = threadIdx.x;
    const float4* fr = (const float4*)(feat + (size_t)row * DIM);
    float4 v = fr[tid];
    float ss = v.x * v.x + v.y * v.y + v.z * v.z + v.w * v.w;
    __shared__ float sh[8];
    #pragma unroll
    for (int o = 16; o > 0; o >>= 1) ss += __shfl_down_sync(0xffffffffu, ss, o);
    if ((tid & 31) == 0) sh[tid >> 5] = ss;
    __syncthreads();
    if (tid < 32) {
        float s = (tid < 8) ? sh[tid] : 0.f;
        #pragma unroll
        for (int o = 4; o > 0; o >>= 1) s += __shfl_down_sync(0xffffffffu, s, o);
        if (tid == 0) sh[0] = s;
    }
    __syncthreads();
    float inv = 1.0f / fmaxf(sqrtf(sh[0]), 1e-12f);
    __nv_bfloat162 lo = __floats2bfloat162_rn(v.x * inv, v.y * inv);
    __nv_bfloat162 hi = __floats2bfloat162_rn(v.z * inv, v.w * inv);
    uint2 pk = make_uint2(*(unsigned*)&lo, *(unsigned*)&hi);
    ((uint2*)(g_fbf + (size_t)row * DIM))[tid] = pk;
    if (tid == 0) {
        g_rowsum[row] = 0.f;
        if (row == 0) g_possum = 0.f;
    }
}

// ---------------- helpers
__device__ __forceinline__ void ldsm_x4(unsigned& r0, unsigned& r1, unsigned& r2,
                                        unsigned& r3, unsigned addr) {
    asm volatile("ldmatrix.sync.aligned.m8n8.x4.shared.b16 {%0,%1,%2,%3}, [%4];"
                 : "=r"(r0), "=r"(r1), "=r"(r2), "=r"(r3) : "r"(addr));
}
__device__ __forceinline__ void mma16816(float* c, const unsigned* a, const unsigned* b) {
    asm volatile(
        "mma.sync.aligned.m16n8k16.row.col.f32.bf16.bf16.f32 "
        "{%0,%1,%2,%3}, {%4,%5,%6,%7}, {%8,%9}, {%0,%1,%2,%3};"
        : "+f"(c[0]), "+f"(c[1]), "+f"(c[2]), "+f"(c[3])
        : "r"(a[0]), "r"(a[1]), "r"(a[2]), "r"(a[3]), "r"(b[0]), "r"(b[1]));
}
__device__ __forceinline__ void cpasync16(unsigned dst, const void* src) {
    asm volatile("cp.async.cg.shared.global [%0], [%1], 16;" :: "r"(dst), "l"(src));
}

// ---------------- Kernel 2: 128x128 tiles, mma.sync, register epilogue
__global__ __launch_bounds__(256) void sim_kernel(const int* __restrict__ targets) {
    int bi = blockIdx.y, bj = blockIdx.x;
    if (bj < bi) return;
    int tid = threadIdx.x;
    int lane = tid & 31, warp = tid >> 5;
    int wr = warp >> 1;   // 0..3 -> 32-row strip
    int wc = warp & 1;    // 0..1 -> 64-col strip

    __shared__ __align__(16) __nv_bfloat16 As[2 * BUFSZ];
    __shared__ __align__(16) __nv_bfloat16 Bs[2 * BUFSZ];
    __shared__ float rowbuf[BT], colbuf[BT];
    __shared__ int Li[BT], Lj[BT];
    __shared__ float pred[8];

    if (tid < BT) { Li[tid] = targets[bi * BT + tid]; rowbuf[tid] = 0.f; colbuf[tid] = 0.f; }
    else          { Lj[tid - BT] = targets[bj * BT + (tid - BT)]; }

    const __nv_bfloat16* FA = g_fbf + (size_t)bi * BT * DIM;
    const __nv_bfloat16* FB = g_fbf + (size_t)bj * BT * DIM;
    unsigned sA = (unsigned)__cvta_generic_to_shared(As);
    unsigned sB = (unsigned)__cvta_generic_to_shared(Bs);

    float acc[2][8][4];
    #pragma unroll
    for (int mi = 0; mi < 2; mi++)
        #pragma unroll
        for (int ni = 0; ni < 8; ni++)
            #pragma unroll
            for (int e = 0; e < 4; e++) acc[mi][ni][e] = 0.f;

    // load thread mapping: 2 x 16B per operand per chunk
    int r0i = tid >> 2, c8 = (tid & 3) * 8;   // rows 0..63
    // prologue: chunk 0 into buf 0
    {
        #pragma unroll
        for (int t = 0; t < 2; t++) {
            int r = r0i + t * 64;
            cpasync16(sA + (r * LDA + c8) * 2, FA + (size_t)r * DIM + c8);
            cpasync16(sB + (r * LDA + c8) * 2, FB + (size_t)r * DIM + c8);
        }
        asm volatile("cp.async.commit_group;");
    }

    for (int c = 0; c < NCHUNK; c++) {
        int buf = c & 1;
        if (c + 1 < NCHUNK) {
            int k0 = (c + 1) * KC;
            unsigned off = (buf ^ 1) * BUFSZ * 2;  // bytes
            #pragma unroll
            for (int t = 0; t < 2; t++) {
                int r = r0i + t * 64;
                cpasync16(sA + off + (r * LDA + c8) * 2, FA + (size_t)r * DIM + k0 + c8);
                cpasync16(sB + off + (r * LDA + c8) * 2, FB + (size_t)r * DIM + k0 + c8);
            }
            asm volatile("cp.async.commit_group;");
            asm volatile("cp.async.wait_group 1;");
        } else {
            asm volatile("cp.async.wait_group 0;");
        }
        __syncthreads();

        unsigned baseA = sA + buf * BUFSZ * 2;
        unsigned baseB = sB + buf * BUFSZ * 2;
        #pragma unroll
        for (int kk = 0; kk < KC; kk += 16) {
            unsigned a[2][4];
            #pragma unroll
            for (int mi = 0; mi < 2; mi++) {
                int row = wr * 32 + mi * 16 + (lane & 7) + ((lane >> 3) & 1) * 8;
                int col = kk + (lane >> 4) * 8;
                ldsm_x4(a[mi][0], a[mi][1], a[mi][2], a[mi][3],
                        baseA + (row * LDA + col) * 2);
            }
            unsigned b[4][4];
            #pragma unroll
            for (int p = 0; p < 4; p++) {
                int row = wc * 64 + p * 16 + (lane & 7) + ((lane >> 4) ? 8 : 0);
                int col = kk + ((lane >> 3) & 1) * 8;
                ldsm_x4(b[p][0], b[p][1], b[p][2], b[p][3],
                        baseB + (row * LDA + col) * 2);
            }
            #pragma unroll
            for (int mi = 0; mi < 2; mi++)
                #pragma unroll
                for (int ni = 0; ni < 8; ni++) {
                    unsigned bb[2];
                    bb[0] = b[ni >> 1][(ni & 1) * 2];
                    bb[1] = b[ni >> 1][(ni & 1) * 2 + 1];
                    mma16816(acc[mi][ni], a[mi], bb);
                }
        }
        __syncthreads();
    }

    // ---- register epilogue: exp, label match, row sums; overwrite acc with e
    int gID = lane >> 2, t4 = lane & 3;
    float psum = 0.f;
    #pragma unroll
    for (int mi = 0; mi < 2; mi++) {
        int row0 = wr * 32 + mi * 16 + gID;
        int row1 = row0 + 8;
        int gi0 = bi * BT + row0, gi1 = bi * BT + row1;
        int li0 = Li[row0], li1 = Li[row1];
        float rs0 = 0.f, rs1 = 0.f;
        #pragma unroll
        for (int ni = 0; ni < 8; ni++) {
            #pragma unroll
            for (int par = 0; par < 2; par++) {
                int col = wc * 64 + ni * 8 + t4 * 2 + par;
                int gj = bj * BT + col;
                int lj = Lj[col];
                float e0 = (gi0 == gj) ? 0.f : __expf(acc[mi][ni][par] * 10.f);
                float e1 = (gi1 == gj) ? 0.f : __expf(acc[mi][ni][par + 2] * 10.f);
                acc[mi][ni][par] = e0;
                acc[mi][ni][par + 2] = e1;
                rs0 += e0;
                rs1 += e1;
                if (li0 == lj) psum += e0;
                if (li1 == lj) psum += e1;
            }
        }
        rs0 += __shfl_xor_sync(0xffffffffu, rs0, 1);
        rs0 += __shfl_xor_sync(0xffffffffu, rs0, 2);
        rs1 += __shfl_xor_sync(0xffffffffu, rs1, 1);
        rs1 += __shfl_xor_sync(0xffffffffu, rs1, 2);
        if (t4 == 0) {
            atomicAdd(&rowbuf[row0], rs0);
            atomicAdd(&rowbuf[row1], rs1);
        }
    }

    // column sums (only needed for off-diagonal tiles: symmetric contribution)
    if (bi != bj) {
        #pragma unroll
        for (int ni = 0; ni < 8; ni++) {
            #pragma unroll
            for (int par = 0; par < 2; par++) {
                float cs = acc[0][ni][par] + acc[0][ni][par + 2]
                         + acc[1][ni][par] + acc[1][ni][par + 2];
                cs += __shfl_xor_sync(0xffffffffu, cs, 4);
                cs += __shfl_xor_sync(0xffffffffu, cs, 8);
                cs += __shfl_xor_sync(0xffffffffu, cs, 16);
                if (gID == 0)
                    atomicAdd(&colbuf[wc * 64 + ni * 8 + t4 * 2 + par], cs);
            }
        }
        psum *= 2.f;
    }

    // block-reduce psum -> one global atomic
    #pragma unroll
    for (int o = 16; o > 0; o >>= 1) psum += __shfl_down_sync(0xffffffffu, psum, o);
    if (lane == 0) pred[warp] = psum;
    __syncthreads();
    if (tid < 32) {
        float v = (tid < 8) ? pred[tid] : 0.f;
        #pragma unroll
        for (int o = 4; o > 0; o >>= 1) v += __shfl_down_sync(0xffffffffu, v, o);
        if (tid == 0) atomicAdd(&g_possum, v);
    }
    if (tid < BT) {
        atomicAdd(&g_rowsum[bi * BT + tid], rowbuf[tid]);
        if (bi != bj) atomicAdd(&g_rowsum[bj * BT + tid], colbuf[tid]);
    }
}

// ---------------- Kernel 3: finalize
__global__ void finalize_kernel(float* __restrict__ out) {
    int tid = threadIdx.x;
    double s = 0.0;
    for (int i = tid; i < NROWS; i += 256) s += log((double)g_rowsum[i]);
    __shared__ double sh[8];
    #pragma unroll
    for (int o = 16; o > 0; o >>= 1) s += __shfl_down_sync(0xffffffffu, s, o);
    if ((tid & 31) == 0) sh[tid >> 5] = s;
    __syncthreads();
    if (tid == 0) {
        double t = 0.0;
        #pragma unroll
        for (int i = 0; i < 8; i++) t += sh[i];
        out[0] = (float)(t / (double)NROWS - log((double)g_possum));
    }
}

extern "C" void kernel_launch(void* const* d_in, const int* in_sizes, int n_in,
                              void* d_out, int out_size) {
    const float* feat = (const float*)d_in[0];
    const int* tgt = (const int*)d_in[1];
    normalize_kernel<<<NROWS, 256>>>(feat);
    dim3 grid(GTILES, GTILES);
    sim_kernel<<<grid, 256>>>(tgt);
    finalize_kernel<<<1, 256>>>((float*)d_out);
}